// round 1
// baseline (speedup 1.0000x reference)
#include <cuda_runtime.h>
#include <cstdint>

#define MQ     50000
#define NSUP   100000
#define HN     32
#define KPN    15
#define CIN    64
#define COUT   64
#define MB     16
#define NTHR   256
#define INFPT  1.0e6f

// smem layout (floats/words):
//  w_s      [MB][HN][16]   = 8192
//  wgt_s    [MB][KPN][CIN] = 15360
//  kp_s     [48]
//  inv_s    [MB]
//  idx_s    [MB][HN] (int) = 512
#define SMEM_WORDS (MB*HN*16 + MB*KPN*CIN + 48 + MB + MB*HN)
#define SMEM_BYTES (SMEM_WORDS * 4)

__device__ int g_idx_is64;

// Detect whether neighbor_indices is int64 (high 32 bits of first 64 values all
// zero -> int64; values are in [0, N] so this is unambiguous in practice).
__global__ void detect_kernel(const unsigned* __restrict__ nbr) {
    if (threadIdx.x == 0) {
        int is64 = 1;
        #pragma unroll
        for (int i = 0; i < 64; i++) {
            if (nbr[2 * i + 1] != 0u) { is64 = 0; break; }
        }
        g_idx_is64 = is64;
    }
}

extern "C" __global__ void __launch_bounds__(NTHR, 2)
kpconv_kernel(const float* __restrict__ qpts,
              const float* __restrict__ spts,
              const float* __restrict__ sfeats,
              const void*  __restrict__ nbr,
              const float* __restrict__ wts,
              const float* __restrict__ kpts,
              float* __restrict__ out)
{
    extern __shared__ float sm[];
    float* w_s   = sm;                          // [MB][HN][16]
    float* wgt_s = sm + MB * HN * 16;           // [MB][KPN][CIN]
    float* kp_s  = wgt_s + MB * KPN * CIN;      // 48
    float* inv_s = kp_s + 48;                   // MB
    int*   idx_s = (int*)(inv_s + MB);          // [MB][HN]

    const int tid = threadIdx.x;
    const int m0  = blockIdx.x * MB;
    const bool is64 = (g_idx_is64 != 0);

    if (tid < KPN * 3) kp_s[tid] = kpts[tid];
    __syncthreads();

    // ---------------- Stage A: geometry weights w[m,h,k] -> smem ------------
    #pragma unroll
    for (int p = tid; p < MB * HN; p += NTHR) {
        const int m = p >> 5;
        const int h = p & 31;
        const long long gi = (long long)(m0 + m) * HN + h;
        int idx;
        if (is64) idx = (int)((const long long*)nbr)[gi];
        else      idx = ((const int*)nbr)[gi];
        idx_s[p] = idx;

        float px, py, pz;
        if (idx < NSUP) {
            const float* s3 = spts + (long long)idx * 3;
            px = s3[0]; py = s3[1]; pz = s3[2];
        } else {
            px = INFPT; py = INFPT; pz = INFPT;
        }
        const float* q3 = qpts + (long long)(m0 + m) * 3;
        const float rx = px - q3[0];
        const float ry = py - q3[1];
        const float rz = pz - q3[2];

        float* wrow = w_s + p * 16;
        float wmax = 0.0f;
        #pragma unroll
        for (int k = 0; k < KPN; k++) {
            const float dx = rx - kp_s[k * 3 + 0];
            const float dy = ry - kp_s[k * 3 + 1];
            const float dz = rz - kp_s[k * 3 + 2];
            const float sq = dx * dx + dy * dy + dz * dz;
            const float w  = fmaxf(1.0f - sqrtf(sq) * 0.5f, 0.0f);
            wrow[k] = w;
            wmax = fmaxf(wmax, w);
        }
        wrow[15] = wmax;
    }
    __syncthreads();

    // ---------------- Stage B: weighted[m,k,c] = sum_h w * f ---------------
    {
        const int g  = tid >> 4;   // query within block
        const int j  = tid & 15;   // channel group
        const int c0 = j * 4;

        float acc[KPN][4];
        #pragma unroll
        for (int k = 0; k < KPN; k++) {
            acc[k][0] = 0.0f; acc[k][1] = 0.0f; acc[k][2] = 0.0f; acc[k][3] = 0.0f;
        }
        int cnt = 0;
        const int*   irow  = idx_s + g * HN;
        const float* wbase = w_s + g * HN * 16;

        #pragma unroll 4
        for (int h = 0; h < HN; h++) {
            const int idx = irow[h];
            float4 f;
            if (idx < NSUP) {
                f = *(const float4*)(sfeats + (long long)idx * CIN + c0);
            } else {
                f = make_float4(0.0f, 0.0f, 0.0f, 0.0f);
            }
            // neighbor counting: sum of ALL 64 channels > 0
            float s = (f.x + f.y) + (f.z + f.w);
            s += __shfl_xor_sync(0xffffffffu, s, 1, 16);
            s += __shfl_xor_sync(0xffffffffu, s, 2, 16);
            s += __shfl_xor_sync(0xffffffffu, s, 4, 16);
            s += __shfl_xor_sync(0xffffffffu, s, 8, 16);
            cnt += (s > 0.0f) ? 1 : 0;

            const float* wr = wbase + h * 16;
            const float wmax = wr[15];
            if (wmax > 0.0f) {
                float wk[16];
                *(float4*)&wk[0]  = *(const float4*)(wr + 0);
                *(float4*)&wk[4]  = *(const float4*)(wr + 4);
                *(float4*)&wk[8]  = *(const float4*)(wr + 8);
                *(float4*)&wk[12] = *(const float4*)(wr + 12);
                #pragma unroll
                for (int k = 0; k < KPN; k++) {
                    acc[k][0] = fmaf(wk[k], f.x, acc[k][0]);
                    acc[k][1] = fmaf(wk[k], f.y, acc[k][1]);
                    acc[k][2] = fmaf(wk[k], f.z, acc[k][2]);
                    acc[k][3] = fmaf(wk[k], f.w, acc[k][3]);
                }
            }
        }

        float* wgrow = wgt_s + g * KPN * CIN + c0;
        #pragma unroll
        for (int k = 0; k < KPN; k++) {
            *(float4*)(wgrow + k * CIN) =
                make_float4(acc[k][0], acc[k][1], acc[k][2], acc[k][3]);
        }
        if (j == 0) {
            inv_s[g] = 1.0f / (float)max(cnt, 1);
        }
    }
    __syncthreads();

    // ---------------- Stage C: out[m,d] = sum_{k,c} weighted * W -----------
    {
        const int cg = tid & 15;       // c-group (4 channels)
        const int dq = tid >> 4;       // d-quad
        const int c0 = cg * 4;
        const int d0 = dq * 4;

        float4 acc[MB];
        #pragma unroll
        for (int mb = 0; mb < MB; mb++) acc[mb] = make_float4(0.f, 0.f, 0.f, 0.f);

        #pragma unroll 1
        for (int k = 0; k < KPN; k++) {
            const float* Wb = wts + (long long)(k * CIN + c0) * COUT + d0;
            const float4 Wq0 = *(const float4*)(Wb);
            const float4 Wq1 = *(const float4*)(Wb + COUT);
            const float4 Wq2 = *(const float4*)(Wb + 2 * COUT);
            const float4 Wq3 = *(const float4*)(Wb + 3 * COUT);
            const float* wg = wgt_s + k * CIN + c0;
            #pragma unroll
            for (int mb = 0; mb < MB; mb++) {
                const float4 wv = *(const float4*)(wg + mb * KPN * CIN);
                acc[mb].x = fmaf(wv.x, Wq0.x, acc[mb].x);
                acc[mb].x = fmaf(wv.y, Wq1.x, acc[mb].x);
                acc[mb].x = fmaf(wv.z, Wq2.x, acc[mb].x);
                acc[mb].x = fmaf(wv.w, Wq3.x, acc[mb].x);
                acc[mb].y = fmaf(wv.x, Wq0.y, acc[mb].y);
                acc[mb].y = fmaf(wv.y, Wq1.y, acc[mb].y);
                acc[mb].y = fmaf(wv.z, Wq2.y, acc[mb].y);
                acc[mb].y = fmaf(wv.w, Wq3.y, acc[mb].y);
                acc[mb].z = fmaf(wv.x, Wq0.z, acc[mb].z);
                acc[mb].z = fmaf(wv.y, Wq1.z, acc[mb].z);
                acc[mb].z = fmaf(wv.z, Wq2.z, acc[mb].z);
                acc[mb].z = fmaf(wv.w, Wq3.z, acc[mb].z);
                acc[mb].w = fmaf(wv.x, Wq0.w, acc[mb].w);
                acc[mb].w = fmaf(wv.y, Wq1.w, acc[mb].w);
                acc[mb].w = fmaf(wv.z, Wq2.w, acc[mb].w);
                acc[mb].w = fmaf(wv.w, Wq3.w, acc[mb].w);
            }
        }

        // reduce-scatter across the 16 c-groups; lane cg ends owning query mb==cg
        #pragma unroll
        for (int o = 8; o >= 1; o >>= 1) {
            const bool up = (cg & o) != 0;
            #pragma unroll
            for (int mb = 0; mb < MB; mb++) {
                if ((mb & o) == 0) {
                    const int a = mb, b = mb | o;
                    const float sx = up ? acc[a].x : acc[b].x;
                    const float sy = up ? acc[a].y : acc[b].y;
                    const float sz = up ? acc[a].z : acc[b].z;
                    const float sw = up ? acc[a].w : acc[b].w;
                    const float rx = __shfl_xor_sync(0xffffffffu, sx, o, 16);
                    const float ry = __shfl_xor_sync(0xffffffffu, sy, o, 16);
                    const float rz = __shfl_xor_sync(0xffffffffu, sz, o, 16);
                    const float rw = __shfl_xor_sync(0xffffffffu, sw, o, 16);
                    acc[a].x += up ? 0.0f : rx;   acc[b].x += up ? rx : 0.0f;
                    acc[a].y += up ? 0.0f : ry;   acc[b].y += up ? ry : 0.0f;
                    acc[a].z += up ? 0.0f : rz;   acc[b].z += up ? rz : 0.0f;
                    acc[a].w += up ? 0.0f : rw;   acc[b].w += up ? rw : 0.0f;
                }
            }
        }

        #pragma unroll
        for (int mb = 0; mb < MB; mb++) {
            if (cg == mb) {
                const float inv = inv_s[mb];
                float4 o4;
                o4.x = acc[mb].x * inv;
                o4.y = acc[mb].y * inv;
                o4.z = acc[mb].z * inv;
                o4.w = acc[mb].w * inv;
                *(float4*)(out + (long long)(m0 + mb) * COUT + d0) = o4;
            }
        }
    }
}

extern "C" void kernel_launch(void* const* d_in, const int* in_sizes, int n_in,
                              void* d_out, int out_size) {
    // Robust input mapping by element count (all sizes are distinct).
    const float* qpts = nullptr;   // 150000
    const float* spts = nullptr;   // 300000
    const float* sfeats = nullptr; // 6400000
    const void*  nbr = nullptr;    // 1600000
    const float* wts = nullptr;    // 61440
    const float* kpts = nullptr;   // 45
    for (int i = 0; i < n_in; i++) {
        switch (in_sizes[i]) {
            case MQ * 3:        qpts   = (const float*)d_in[i]; break;
            case NSUP * 3:      spts   = (const float*)d_in[i]; break;
            case NSUP * CIN:    sfeats = (const float*)d_in[i]; break;
            case MQ * HN:       nbr    = d_in[i];               break;
            case KPN*CIN*COUT:  wts    = (const float*)d_in[i]; break;
            case KPN * 3:       kpts   = (const float*)d_in[i]; break;
            default: break;
        }
    }
    float* outp = (float*)d_out;

    cudaFuncSetAttribute(kpconv_kernel,
                         cudaFuncAttributeMaxDynamicSharedMemorySize, SMEM_BYTES);

    detect_kernel<<<1, 32>>>((const unsigned*)nbr);
    kpconv_kernel<<<(MQ + MB - 1) / MB, NTHR, SMEM_BYTES>>>(
        qpts, spts, sfeats, nbr, wts, kpts, outp);
}

// round 2
// speedup vs baseline: 1.3302x; 1.3302x over previous
#include <cuda_runtime.h>
#include <cstdint>

#define MQ     50000
#define NSUP   100000
#define HN     32
#define KPN    15
#define CIN    64
#define COUT   64
#define MB     16
#define NTHR   256
#define INFPT  1.0e6f

// smem layout (floats/words):
//  w_s      [MB][HN][16]   = 8192   (reused as reduction buffer in stage C)
//  wgt_s    [MB][KPN][CIN] = 15360
//  kp_s     [48]
//  inv_s    [MB]
//  idx_s    [MB][HN] (int) = 512
#define SMEM_WORDS (MB*HN*16 + MB*KPN*CIN + 48 + MB + MB*HN)
#define SMEM_BYTES (SMEM_WORDS * 4)

__device__ int g_idx_is64;
__device__ unsigned char g_flags[NSUP];

// Detect whether neighbor_indices is int64 (high 32 bits of first 64 values all
// zero -> int64; values are in [0, N] so this is unambiguous in practice).
__global__ void detect_kernel(const unsigned* __restrict__ nbr) {
    if (threadIdx.x == 0) {
        int is64 = 1;
        #pragma unroll
        for (int i = 0; i < 64; i++) {
            if (nbr[2 * i + 1] != 0u) { is64 = 0; break; }
        }
        g_idx_is64 = is64;
    }
}

// Precompute flag[n] = (sum of 64 channels of sfeats[n] > 0), one warp per row.
__global__ void __launch_bounds__(256) flag_kernel(const float* __restrict__ sfeats) {
    const int n = blockIdx.x * 8 + (threadIdx.x >> 5);
    if (n >= NSUP) return;
    const int lane = threadIdx.x & 31;
    const float* row = sfeats + (long long)n * CIN;
    float s = row[lane] + row[lane + 32];
    #pragma unroll
    for (int o = 16; o; o >>= 1) s += __shfl_xor_sync(0xffffffffu, s, o);
    if (lane == 0) g_flags[n] = (s > 0.0f) ? 1 : 0;
}

extern "C" __global__ void __launch_bounds__(NTHR, 2)
kpconv_kernel(const float* __restrict__ qpts,
              const float* __restrict__ spts,
              const float* __restrict__ sfeats,
              const void*  __restrict__ nbr,
              const float* __restrict__ wts,
              const float* __restrict__ kpts,
              float* __restrict__ out)
{
    extern __shared__ float sm[];
    float* w_s   = sm;                          // [MB][HN][16] then [8][MB][COUT]
    float* wgt_s = sm + MB * HN * 16;           // [MB][KPN][CIN]
    float* kp_s  = wgt_s + MB * KPN * CIN;      // 48
    float* inv_s = kp_s + 48;                   // MB
    int*   idx_s = (int*)(inv_s + MB);          // [MB][HN]

    const int tid = threadIdx.x;
    const int m0  = blockIdx.x * MB;
    const bool is64 = (g_idx_is64 != 0);

    if (tid < KPN * 3) kp_s[tid] = kpts[tid];
    __syncthreads();

    // ---------------- Stage A: geometry weights w[m,h,k] -> smem ------------
    // One warp handles one query (m) per iteration; ballot counts real neighbors.
    #pragma unroll
    for (int it = 0; it < 2; it++) {
        const int p = tid + it * NTHR;          // p < MB*HN = 512
        const int m = p >> 5;
        const int h = p & 31;
        const long long gi = (long long)(m0 + m) * HN + h;
        int idx;
        if (is64) idx = (int)((const long long*)nbr)[gi];
        else      idx = ((const int*)nbr)[gi];
        const bool valid = (idx < NSUP);

        float px, py, pz;
        if (valid) {
            const float* s3 = spts + (long long)idx * 3;
            px = s3[0]; py = s3[1]; pz = s3[2];
        } else {
            px = INFPT; py = INFPT; pz = INFPT;
        }
        const float* q3 = qpts + (long long)(m0 + m) * 3;
        const float rx = px - q3[0];
        const float ry = py - q3[1];
        const float rz = pz - q3[2];

        float* wrow = w_s + p * 16;
        float wmax = 0.0f;
        #pragma unroll
        for (int k = 0; k < KPN; k++) {
            const float dx = rx - kp_s[k * 3 + 0];
            const float dy = ry - kp_s[k * 3 + 1];
            const float dz = rz - kp_s[k * 3 + 2];
            const float sq = dx * dx + dy * dy + dz * dz;
            const float w  = fmaxf(1.0f - sqrtf(sq) * 0.5f, 0.0f);
            wrow[k] = w;
            wmax = fmaxf(wmax, w);
        }

        // neighbor counting: real neighbor iff its 64-channel feature sum > 0
        bool real = false;
        if (valid) real = (g_flags[idx] != 0);
        const unsigned bal = __ballot_sync(0xffffffffu, real);
        if ((tid & 31) == 0) inv_s[m] = 1.0f / (float)max(__popc(bal), 1);

        // store idx only if this neighbor contributes (wmax>0); else sentinel
        idx_s[p] = (wmax > 0.0f) ? idx : -1;
    }
    __syncthreads();

    // ---------------- Stage B: weighted[m,k,c] = sum_h w * f ---------------
    {
        const int g  = tid >> 4;   // query within block
        const int j  = tid & 15;   // channel group
        const int c0 = j * 4;

        float acc[KPN][4];
        #pragma unroll
        for (int k = 0; k < KPN; k++) {
            acc[k][0] = 0.0f; acc[k][1] = 0.0f; acc[k][2] = 0.0f; acc[k][3] = 0.0f;
        }
        const int*   irow  = idx_s + g * HN;
        const float* wbase = w_s + g * HN * 16;

        #pragma unroll 4
        for (int h = 0; h < HN; h++) {
            const int idx = irow[h];
            if (idx >= 0) {
                const float4 f = *(const float4*)(sfeats + (long long)idx * CIN + c0);
                const float* wr = wbase + h * 16;
                float wk[16];
                *(float4*)&wk[0]  = *(const float4*)(wr + 0);
                *(float4*)&wk[4]  = *(const float4*)(wr + 4);
                *(float4*)&wk[8]  = *(const float4*)(wr + 8);
                *(float4*)&wk[12] = *(const float4*)(wr + 12);
                #pragma unroll
                for (int k = 0; k < KPN; k++) {
                    acc[k][0] = fmaf(wk[k], f.x, acc[k][0]);
                    acc[k][1] = fmaf(wk[k], f.y, acc[k][1]);
                    acc[k][2] = fmaf(wk[k], f.z, acc[k][2]);
                    acc[k][3] = fmaf(wk[k], f.w, acc[k][3]);
                }
            }
        }

        float* wgrow = wgt_s + g * KPN * CIN + c0;
        #pragma unroll
        for (int k = 0; k < KPN; k++) {
            *(float4*)(wgrow + k * CIN) =
                make_float4(acc[k][0], acc[k][1], acc[k][2], acc[k][3]);
        }
    }
    __syncthreads();

    // ---------------- Stage C: out[m,d] = sum_{k,c} weighted * W -----------
    // dq fast (coalesced W/out), cg slow. Partial over 4 channels per thread.
    {
        const int dq = tid & 15;       // d-quad (fast -> coalesced LDG of W)
        const int cg = tid >> 4;       // c-group (4 channels)
        const int d0 = dq * 4;
        const int c0 = cg * 4;

        float4 acc[MB];
        #pragma unroll
        for (int mb = 0; mb < MB; mb++) acc[mb] = make_float4(0.f, 0.f, 0.f, 0.f);

        #pragma unroll 1
        for (int k = 0; k < KPN; k++) {
            const float* Wb = wts + (long long)(k * CIN + c0) * COUT + d0;
            const float4 Wq0 = *(const float4*)(Wb);
            const float4 Wq1 = *(const float4*)(Wb + COUT);
            const float4 Wq2 = *(const float4*)(Wb + 2 * COUT);
            const float4 Wq3 = *(const float4*)(Wb + 3 * COUT);
            const float* wg = wgt_s + k * CIN + c0;
            #pragma unroll
            for (int mb = 0; mb < MB; mb++) {
                const float4 wv = *(const float4*)(wg + mb * KPN * CIN);  // broadcast
                acc[mb].x = fmaf(wv.x, Wq0.x, acc[mb].x);
                acc[mb].x = fmaf(wv.y, Wq1.x, acc[mb].x);
                acc[mb].x = fmaf(wv.z, Wq2.x, acc[mb].x);
                acc[mb].x = fmaf(wv.w, Wq3.x, acc[mb].x);
                acc[mb].y = fmaf(wv.x, Wq0.y, acc[mb].y);
                acc[mb].y = fmaf(wv.y, Wq1.y, acc[mb].y);
                acc[mb].y = fmaf(wv.z, Wq2.y, acc[mb].y);
                acc[mb].y = fmaf(wv.w, Wq3.y, acc[mb].y);
                acc[mb].z = fmaf(wv.x, Wq0.z, acc[mb].z);
                acc[mb].z = fmaf(wv.y, Wq1.z, acc[mb].z);
                acc[mb].z = fmaf(wv.z, Wq2.z, acc[mb].z);
                acc[mb].z = fmaf(wv.w, Wq3.z, acc[mb].z);
                acc[mb].w = fmaf(wv.x, Wq0.w, acc[mb].w);
                acc[mb].w = fmaf(wv.y, Wq1.w, acc[mb].w);
                acc[mb].w = fmaf(wv.z, Wq2.w, acc[mb].w);
                acc[mb].w = fmaf(wv.w, Wq3.w, acc[mb].w);
            }
        }

        // pair-reduce cg (2w, 2w+1) within the warp: lane L <-> L^16 share dq
        #pragma unroll
        for (int mb = 0; mb < MB; mb++) {
            acc[mb].x += __shfl_xor_sync(0xffffffffu, acc[mb].x, 16);
            acc[mb].y += __shfl_xor_sync(0xffffffffu, acc[mb].y, 16);
            acc[mb].z += __shfl_xor_sync(0xffffffffu, acc[mb].z, 16);
            acc[mb].w += __shfl_xor_sync(0xffffffffu, acc[mb].w, 16);
        }

        // warp w holds partial over channels [w*8, w*8+8); stash in w_s (reused)
        const int w = tid >> 5;
        if ((tid & 31) < 16) {
            float* dst = w_s + w * (MB * COUT) + d0;
            #pragma unroll
            for (int mb = 0; mb < MB; mb++) {
                *(float4*)(dst + mb * COUT) = acc[mb];
            }
        }
    }
    __syncthreads();

    // final cross-warp reduction + normalize + store
    {
        const int mb = tid >> 4;
        const int d0 = (tid & 15) * 4;
        float4 o = make_float4(0.f, 0.f, 0.f, 0.f);
        #pragma unroll
        for (int w = 0; w < 8; w++) {
            const float4 p = *(const float4*)(w_s + w * (MB * COUT) + mb * COUT + d0);
            o.x += p.x; o.y += p.y; o.z += p.z; o.w += p.w;
        }
        const float inv = inv_s[mb];
        o.x *= inv; o.y *= inv; o.z *= inv; o.w *= inv;
        *(float4*)(out + (long long)(m0 + mb) * COUT + d0) = o;
    }
}

extern "C" void kernel_launch(void* const* d_in, const int* in_sizes, int n_in,
                              void* d_out, int out_size) {
    // Robust input mapping by element count (all sizes are distinct).
    const float* qpts = nullptr;   // 150000
    const float* spts = nullptr;   // 300000
    const float* sfeats = nullptr; // 6400000
    const void*  nbr = nullptr;    // 1600000
    const float* wts = nullptr;    // 61440
    const float* kpts = nullptr;   // 45
    for (int i = 0; i < n_in; i++) {
        switch (in_sizes[i]) {
            case MQ * 3:        qpts   = (const float*)d_in[i]; break;
            case NSUP * 3:      spts   = (const float*)d_in[i]; break;
            case NSUP * CIN:    sfeats = (const float*)d_in[i]; break;
            case MQ * HN:       nbr    = d_in[i];               break;
            case KPN*CIN*COUT:  wts    = (const float*)d_in[i]; break;
            case KPN * 3:       kpts   = (const float*)d_in[i]; break;
            default: break;
        }
    }
    float* outp = (float*)d_out;

    cudaFuncSetAttribute(kpconv_kernel,
                         cudaFuncAttributeMaxDynamicSharedMemorySize, SMEM_BYTES);

    detect_kernel<<<1, 32>>>((const unsigned*)nbr);
    flag_kernel<<<(NSUP + 7) / 8, 256>>>(sfeats);
    kpconv_kernel<<<(MQ + MB - 1) / MB, NTHR, SMEM_BYTES>>>(
        qpts, spts, sfeats, nbr, wts, kpts, outp);
}